// round 1
// baseline (speedup 1.0000x reference)
#include <cuda_runtime.h>
#include <cuda_bf16.h>
#include <math.h>
#include <stdint.h>

#define N_SAMPLES 16384
#define F_DIM 64
#define K_BINS 32
#define M_DIM 2048        // F*K
#define C_DIM 128
#define EPSV 1e-8f
#define SPLITS 16
#define L_CHUNK 1024      // N_SAMPLES / SPLITS

// -------- device scratch (no allocations allowed) --------
__device__ float gS[M_DIM * C_DIM];   // sum_weighted_y (f*K+k, c)
__device__ float gMass[M_DIM];        // sum_n membership
__device__ float gWy[M_DIM];          // sum_n membership * y_sq
__device__ float gYsq[N_SAMPLES];     // per-sample ||y||^2
__device__ float gOut[4];             // disp, ent, rep, inter(raw)

__device__ __forceinline__ float warp_sum(float v) {
    v += __shfl_xor_sync(0xffffffffu, v, 16);
    v += __shfl_xor_sync(0xffffffffu, v, 8);
    v += __shfl_xor_sync(0xffffffffu, v, 4);
    v += __shfl_xor_sync(0xffffffffu, v, 2);
    v += __shfl_xor_sync(0xffffffffu, v, 1);
    return v;
}

__device__ __forceinline__ uint32_t pack_bf16x2(float lo, float hi) {
    __nv_bfloat162 t = __floats2bfloat162_rn(lo, hi);  // x = lo (low 16 bits)
    return *reinterpret_cast<uint32_t*>(&t);
}

__device__ __forceinline__ void mma_bf16(float* d, const uint32_t* a,
                                         uint32_t b0, uint32_t b1) {
    asm volatile(
        "mma.sync.aligned.m16n8k16.row.col.f32.bf16.bf16.f32 "
        "{%0,%1,%2,%3}, {%4,%5,%6,%7}, {%8,%9}, {%0,%1,%2,%3};\n"
        : "+f"(d[0]), "+f"(d[1]), "+f"(d[2]), "+f"(d[3])
        : "r"(a[0]), "r"(a[1]), "r"(a[2]), "r"(a[3]), "r"(b0), "r"(b1));
}

// ---------------- Kernel 0: zero accumulators + y_sq ----------------
__global__ void k0_init(const float* __restrict__ teacher) {
    int tid = threadIdx.x;
    int idx = blockIdx.x * 256 + tid;
    if (idx < M_DIM * C_DIM) gS[idx] = 0.0f;
    if (idx < M_DIM) { gMass[idx] = 0.0f; gWy[idx] = 0.0f; }
    if (idx < 4) gOut[idx] = 0.0f;

    int n = idx >> 5;
    int lane = tid & 31;
    if (n < N_SAMPLES) {
        float4 v = reinterpret_cast<const float4*>(teacher)[n * 32 + lane];
        float s = v.x * v.x + v.y * v.y + v.z * v.z + v.w * v.w;
        s = warp_sum(s);
        if (lane == 0) gYsq[n] = s;
    }
}

// ---------------- Kernel 1: fused bf16-MMA GEMM + mass/wy ----------------
// grid = 16 M-tiles * 16 K-splits = 256 CTAs, 256 threads each.
// CTA computes 128(m) x 128(c) over a 1024-sample n-slice; atomicAdd partials.
__global__ void __launch_bounds__(256, 2)
k1_main(const float* __restrict__ membership, const float* __restrict__ teacher) {
    // [qpair 0..15][m 0..127] packed bf16x2 (consecutive n in low/high halves)
    __shared__ uint32_t Apack[16][132];
    __shared__ uint32_t Bpack[16][132];
    __shared__ float s_ysq[32];
    __shared__ float s_red[256];

    int tid = threadIdx.x;
    int mt = blockIdx.x & 15;
    int sp = blockIdx.x >> 4;
    int m0 = mt * 128;
    int nbeg = sp * L_CHUNK;

    int w = tid >> 5, lane = tid & 31;
    int m_off = (w & 3) * 32;      // warp tile: 32 m x 64 c
    int c_off = (w >> 2) * 64;
    int lr = lane >> 2, lc = lane & 3;

    // staging assignment: q = row-pair, g = 16-byte group index
    int q = tid >> 4;  // 0..15
    int g = tid & 15;  // 0..15

    float d[2][8][4];
#pragma unroll
    for (int i = 0; i < 2; ++i)
#pragma unroll
        for (int j = 0; j < 8; ++j)
#pragma unroll
            for (int t = 0; t < 4; ++t) d[i][j][t] = 0.0f;

    float massA = 0.0f, wyA = 0.0f;
    int mmy = tid & 127;   // m owned for mass/wy
    int h = tid >> 7;      // which half of the q-range

    for (int it = 0; it < L_CHUNK / 32; ++it) {
        int n0 = nbeg + it * 32;
        __syncthreads();
        // ---- stage A (membership: n-major, m contiguous) ----
        {
            const float* base = membership + (size_t)(n0 + 2 * q) * M_DIM + m0;
            float4 r0 = *(const float4*)(base + g * 4);
            float4 r1 = *(const float4*)(base + M_DIM + g * 4);
            uint4 pk;
            pk.x = pack_bf16x2(r0.x, r1.x);
            pk.y = pack_bf16x2(r0.y, r1.y);
            pk.z = pack_bf16x2(r0.z, r1.z);
            pk.w = pack_bf16x2(r0.w, r1.w);
            *(uint4*)&Apack[q][g * 4] = pk;
            float4 r2 = *(const float4*)(base + (g + 16) * 4);
            float4 r3 = *(const float4*)(base + M_DIM + (g + 16) * 4);
            pk.x = pack_bf16x2(r2.x, r3.x);
            pk.y = pack_bf16x2(r2.y, r3.y);
            pk.z = pack_bf16x2(r2.z, r3.z);
            pk.w = pack_bf16x2(r2.w, r3.w);
            *(uint4*)&Apack[q][64 + g * 4] = pk;
        }
        // ---- stage B (teacher: n-major, c contiguous) ----
        {
            const float* base = teacher + (size_t)(n0 + 2 * q) * C_DIM;
            float4 r0 = *(const float4*)(base + g * 4);
            float4 r1 = *(const float4*)(base + C_DIM + g * 4);
            uint4 pk;
            pk.x = pack_bf16x2(r0.x, r1.x);
            pk.y = pack_bf16x2(r0.y, r1.y);
            pk.z = pack_bf16x2(r0.z, r1.z);
            pk.w = pack_bf16x2(r0.w, r1.w);
            *(uint4*)&Bpack[q][g * 4] = pk;
            float4 r2 = *(const float4*)(base + (g + 16) * 4);
            float4 r3 = *(const float4*)(base + C_DIM + (g + 16) * 4);
            pk.x = pack_bf16x2(r2.x, r3.x);
            pk.y = pack_bf16x2(r2.y, r3.y);
            pk.z = pack_bf16x2(r2.z, r3.z);
            pk.w = pack_bf16x2(r2.w, r3.w);
            *(uint4*)&Bpack[q][64 + g * 4] = pk;
        }
        if (tid < 32) s_ysq[tid] = gYsq[n0 + tid];
        __syncthreads();

        // ---- fp32 mass / wy from staged bf16 ----
#pragma unroll
        for (int qq = 0; qq < 8; ++qq) {
            int qi = h * 8 + qq;
            uint32_t p = Apack[qi][mmy];
            __nv_bfloat162 bb = *reinterpret_cast<__nv_bfloat162*>(&p);
            float ae = __bfloat162float(bb.x);
            float ao = __bfloat162float(bb.y);
            massA += ae + ao;
            wyA += ae * s_ysq[2 * qi] + ao * s_ysq[2 * qi + 1];
        }

        // ---- 2 k-sub-steps (k=16 each) x 16 mmas ----
#pragma unroll
        for (int ks = 0; ks < 2; ++ks) {
            int qb = ks * 8;
            uint32_t af[2][4];
#pragma unroll
            for (int mt2 = 0; mt2 < 2; ++mt2) {
                int mr = m_off + mt2 * 16 + lr;
                af[mt2][0] = Apack[qb + lc][mr];
                af[mt2][1] = Apack[qb + lc][mr + 8];
                af[mt2][2] = Apack[qb + 4 + lc][mr];
                af[mt2][3] = Apack[qb + 4 + lc][mr + 8];
            }
#pragma unroll
            for (int ct = 0; ct < 8; ++ct) {
                int cr = c_off + ct * 8 + lr;
                uint32_t b0 = Bpack[qb + lc][cr];
                uint32_t b1 = Bpack[qb + 4 + lc][cr];
                mma_bf16(d[0][ct], af[0], b0, b1);
                mma_bf16(d[1][ct], af[1], b0, b1);
            }
        }
    }

    // ---- epilogue: reduce mass/wy halves, atomicAdd everything ----
    __syncthreads();
    s_red[tid] = massA;
    __syncthreads();
    if (tid < 128) atomicAdd(&gMass[m0 + tid], massA + s_red[tid + 128]);
    __syncthreads();
    s_red[tid] = wyA;
    __syncthreads();
    if (tid < 128) atomicAdd(&gWy[m0 + tid], wyA + s_red[tid + 128]);

#pragma unroll
    for (int mt2 = 0; mt2 < 2; ++mt2) {
#pragma unroll
        for (int ct = 0; ct < 8; ++ct) {
#pragma unroll
            for (int i = 0; i < 4; ++i) {
                int row = m0 + m_off + mt2 * 16 + lr + ((i >> 1) * 8);
                int col = c_off + ct * 8 + lc * 2 + (i & 1);
                atomicAdd(&gS[row * C_DIM + col], d[mt2][ct][i]);
            }
        }
    }
}

// ---------------- Kernel 2: per-feature finalize ----------------
__global__ void k2_finalize() {
    __shared__ float cent[K_BINS][C_DIM];
    __shared__ float s_csq[K_BINS];
    __shared__ float wRep[8];
    __shared__ float wInt[8];

    int f = blockIdx.x;
    int tid = threadIdx.x;
    int w = tid >> 5, lane = tid & 31;

    for (int idx = tid; idx < K_BINS * C_DIM; idx += 256) {
        int k = idx >> 7;
        int c = idx & 127;
        float bm = gMass[f * K_BINS + k] + EPSV;
        cent[k][c] = gS[(f * K_BINS + k) * C_DIM + c] / bm;
    }
    __syncthreads();

    // c_sq per bin
    for (int k = w; k < K_BINS; k += 8) {
        float s = 0.0f;
#pragma unroll
        for (int j = 0; j < 4; ++j) {
            float v = cent[k][lane + 32 * j];
            s += v * v;
        }
        s = warp_sum(s);
        if (lane == 0) s_csq[k] = s;
    }
    __syncthreads();

    // dispersion + entropy (warp 0, one lane per bin)
    if (w == 0) {
        int k = lane;
        float bm = gMass[f * K_BINS + k] + EPSV;
        float wv = gWy[f * K_BINS + k] / bm - s_csq[k] * (1.0f + EPSV / bm);
        float p = bm / (float)N_SAMPLES;
        float ent = p * logf(p + EPSV);
        float dsum = warp_sum(wv);
        float esum = warp_sum(ent);
        if (lane == 0) {
            atomicAdd(&gOut[0], dsum);
            atomicAdd(&gOut[1], esum);
        }
    }

    // neighbor repulsion: 31 adjacent pairs
    float repP = 0.0f;
    for (int p = w; p < K_BINS - 1; p += 8) {
        float s = 0.0f;
#pragma unroll
        for (int j = 0; j < 4; ++j) {
            int c = lane + 32 * j;
            float dd = cent[p][c] - cent[p + 1][c];
            s += dd * dd;
        }
        s = warp_sum(s);
        if (lane == 0) repP += expf(-s);  // TEMPERATURE = 1
    }

    // all-pairs inter-bin (strict upper triangle)
    float intP = 0.0f;
    for (int k = 0; k < K_BINS - 1; ++k) {
        for (int j = k + 1 + w; j < K_BINS; j += 8) {
            float s = 0.0f;
#pragma unroll
            for (int jj = 0; jj < 4; ++jj) {
                int c = lane + 32 * jj;
                float dd = cent[k][c] - cent[j][c];
                s += dd * dd;
            }
            s = warp_sum(s);
            if (lane == 0) intP += expf(-s);
        }
    }
    if (lane == 0) { wRep[w] = repP; wInt[w] = intP; }
    __syncthreads();
    if (tid == 0) {
        float rep = 0.0f, inter = 0.0f;
        for (int i = 0; i < 8; ++i) { rep += wRep[i]; inter += wInt[i]; }
        atomicAdd(&gOut[2], rep);
        atomicAdd(&gOut[3], inter);
    }
}

// ---------------- Kernel 3: assemble outputs ----------------
__global__ void k3_write(float* out, int out_size) {
    if (threadIdx.x == 0 && blockIdx.x == 0) {
        float disp  = gOut[0];
        float ent   = gOut[1];
        float rep   = gOut[2];
        float inter = gOut[3] / (float)F_DIM;
        float total = disp + 0.1f * ent + 0.5f * rep + 0.3f * inter;
        float vals[5] = {total, disp, ent, rep, inter};
        for (int i = 0; i < out_size; ++i) out[i] = (i < 5) ? vals[i] : 0.0f;
    }
}

extern "C" void kernel_launch(void* const* d_in, const int* in_sizes, int n_in,
                              void* d_out, int out_size) {
    const float* p0 = (const float*)d_in[0];
    const float* p1 = (const float*)d_in[1];
    const float* membership = p0;
    const float* teacher = p1;
    if (n_in >= 2 && in_sizes[0] < in_sizes[1]) {  // membership is the big one
        membership = p1;
        teacher = p0;
    }
    k0_init<<<2048, 256>>>(teacher);
    k1_main<<<SPLITS * 16, 256>>>(membership, teacher);
    k2_finalize<<<F_DIM, 256>>>();
    k3_write<<<1, 1>>>((float*)d_out, out_size);
}

// round 2
// speedup vs baseline: 1.1238x; 1.1238x over previous
#include <cuda_runtime.h>
#include <cuda_bf16.h>
#include <math.h>
#include <stdint.h>

#define N_SAMPLES 16384
#define F_DIM 64
#define K_BINS 32
#define M_DIM 2048        // F*K
#define C_DIM 128
#define EPSV 1e-8f
#define SPLITS 16
#define L_CHUNK 1024      // N_SAMPLES / SPLITS
#define NIT 32            // L_CHUNK / 32

// ---- dynamic smem layout (bytes) ----
// A fp32 double buffer: 2 x [32][132] floats = 33792
// B bf16x2 double buffer: 2 x [16][136] u32  = 17408
// ysq double buffer: 2 x [32] floats         = 256
// reduction buffer: [256] floats             = 1024
#define SM_A     0
#define SM_B     33792
#define SM_Y     51200
#define SM_R     51456
#define SM_TOTAL 52480
#define A_BUF_F  4224      // floats per A buffer (32*132)
#define B_BUF_W  2176      // u32 per B buffer (16*136)

// -------- device scratch --------
__device__ float    gS[M_DIM * C_DIM];
__device__ float    gMass[M_DIM];
__device__ float    gWy[M_DIM];
__device__ float    gYsq[N_SAMPLES];
__device__ uint32_t gTpack[(N_SAMPLES / 2) * C_DIM];  // teacher bf16, n-pairs packed
__device__ float    gOut[4];
__device__ int      gDone;

__device__ __forceinline__ float warp_sum(float v) {
    v += __shfl_xor_sync(0xffffffffu, v, 16);
    v += __shfl_xor_sync(0xffffffffu, v, 8);
    v += __shfl_xor_sync(0xffffffffu, v, 4);
    v += __shfl_xor_sync(0xffffffffu, v, 2);
    v += __shfl_xor_sync(0xffffffffu, v, 1);
    return v;
}

__device__ __forceinline__ uint32_t pack_bf16x2(float lo, float hi) {
    __nv_bfloat162 t = __floats2bfloat162_rn(lo, hi);
    return *reinterpret_cast<uint32_t*>(&t);
}

__device__ __forceinline__ void mma_bf16(float* d, const uint32_t* a,
                                         uint32_t b0, uint32_t b1) {
    asm volatile(
        "mma.sync.aligned.m16n8k16.row.col.f32.bf16.bf16.f32 "
        "{%0,%1,%2,%3}, {%4,%5,%6,%7}, {%8,%9}, {%0,%1,%2,%3};\n"
        : "+f"(d[0]), "+f"(d[1]), "+f"(d[2]), "+f"(d[3])
        : "r"(a[0]), "r"(a[1]), "r"(a[2]), "r"(a[3]), "r"(b0), "r"(b1));
}

__device__ __forceinline__ void cp16(uint32_t dst, const void* src) {
    asm volatile("cp.async.cg.shared.global [%0], [%1], 16;\n" :: "r"(dst), "l"(src));
}

// ---------------- Kernel 0: zero + y_sq + prepack teacher ----------------
__global__ void k0_init(const float* __restrict__ teacher) {
    int tid = threadIdx.x;
    int idx = blockIdx.x * 256 + tid;            // 0 .. 524287
    if (idx < M_DIM * C_DIM) gS[idx] = 0.0f;
    if (idx < M_DIM) { gMass[idx] = 0.0f; gWy[idx] = 0.0f; }
    if (idx < 4) gOut[idx] = 0.0f;
    if (idx == 4) gDone = 0;

    // y_sq: one warp per sample row
    int n = idx >> 5;
    int lane = tid & 31;
    if (n < N_SAMPLES) {
        float4 v = reinterpret_cast<const float4*>(teacher)[n * 32 + lane];
        float s = v.x * v.x + v.y * v.y + v.z * v.z + v.w * v.w;
        s = warp_sum(s);
        if (lane == 0) gYsq[n] = s;
    }

    // prepack teacher: 1,048,576 words, 2 per thread
#pragma unroll
    for (int j = 0; j < 2; ++j) {
        int w = idx + j * 524288;
        int np = w >> 7;
        int c = w & 127;
        gTpack[w] = pack_bf16x2(teacher[(2 * np) * C_DIM + c],
                                teacher[(2 * np + 1) * C_DIM + c]);
    }
}

// ---------------- Kernel 1: pipelined bf16-MMA GEMM + mass/wy ----------------
__global__ void __launch_bounds__(256, 2)
k1_main(const float* __restrict__ membership) {
    extern __shared__ char smem[];
    uint32_t sb = (uint32_t)__cvta_generic_to_shared(smem);

    int tid = threadIdx.x;
    int mt = blockIdx.x & 15;
    int sp = blockIdx.x >> 4;
    int m0 = mt * 128;
    int nbeg = sp * L_CHUNK;

    int w = tid >> 5, lane = tid & 31;
    int m_off = (w & 3) * 32;
    int c_off = (w >> 2) * 64;
    int lr = lane >> 2, lc = lane & 3;

    int mmy = tid & 127;
    int h = tid >> 7;

    float d[2][8][4];
#pragma unroll
    for (int i = 0; i < 2; ++i)
#pragma unroll
        for (int j = 0; j < 8; ++j)
#pragma unroll
            for (int t = 0; t < 4; ++t) d[i][j][t] = 0.0f;
    float massA = 0.0f, wyA = 0.0f;

    // staging indices
    int sr = tid >> 3;   // 0..31  (A row)
    int scg = tid & 7;   // 0..7   (A 16B chunk group)

    auto stage = [&](int it, int buf) {
        int n0 = nbeg + it * 32;
        // A: 32 rows x 128 floats (fp32), 4 chunks/thread, octet-conflict-free
        const float* srcA = membership + (size_t)(n0 + sr) * M_DIM + m0 + scg * 4;
        uint32_t dA = sb + SM_A + buf * (A_BUF_F * 4) + sr * 528 + scg * 16;
        cp16(dA, srcA);
        cp16(dA + 128, srcA + 32);
        cp16(dA + 256, srcA + 64);
        cp16(dA + 384, srcA + 96);
        // B: 16 qpair rows x 128 u32 from gTpack, 2 chunks/thread
        int np0 = n0 >> 1;
        {
            int row = tid >> 5, cc = tid & 31;
            cp16(sb + SM_B + buf * (B_BUF_W * 4) + row * 544 + cc * 16,
                 gTpack + (np0 + row) * C_DIM + cc * 4);
            int cid = tid + 256;
            row = cid >> 5; cc = cid & 31;
            cp16(sb + SM_B + buf * (B_BUF_W * 4) + row * 544 + cc * 16,
                 gTpack + (np0 + row) * C_DIM + cc * 4);
        }
        // ysq: 32 floats
        if (tid < 8)
            cp16(sb + SM_Y + buf * 128 + tid * 16, gYsq + n0 + tid * 4);
    };

    stage(0, 0);
    asm volatile("cp.async.commit_group;\n");

    for (int it = 0; it < NIT; ++it) {
        int cur = it & 1;
        if (it + 1 < NIT) {
            stage(it + 1, cur ^ 1);
            asm volatile("cp.async.commit_group;\n");
            asm volatile("cp.async.wait_group 1;\n");
        } else {
            asm volatile("cp.async.wait_group 0;\n");
        }
        __syncthreads();

        const float* As = (const float*)(smem) + cur * A_BUF_F;
        const uint32_t* Bs = (const uint32_t*)(smem + SM_B) + cur * B_BUF_W;
        const float* Ys = (const float*)(smem + SM_Y) + cur * 32;

        // ---- fp32 mass / wy ----
#pragma unroll
        for (int qq = 0; qq < 8; ++qq) {
            int qi = h * 8 + qq;
            float ae = As[(2 * qi) * 132 + mmy];
            float ao = As[(2 * qi + 1) * 132 + mmy];
            massA += ae + ao;
            wyA += ae * Ys[2 * qi] + ao * Ys[2 * qi + 1];
        }

        // ---- MMA: 2 k-sub-steps x 16 mmas ----
#pragma unroll
        for (int ks = 0; ks < 2; ++ks) {
            int qb = ks * 8;
            uint32_t af[2][4];
#pragma unroll
            for (int mt2 = 0; mt2 < 2; ++mt2) {
                int mr = m_off + mt2 * 16 + lr;
                int ra = 2 * (qb + lc) * 132;
                int rb = 2 * (qb + 4 + lc) * 132;
                af[mt2][0] = pack_bf16x2(As[ra + mr], As[ra + 132 + mr]);
                af[mt2][1] = pack_bf16x2(As[ra + mr + 8], As[ra + 132 + mr + 8]);
                af[mt2][2] = pack_bf16x2(As[rb + mr], As[rb + 132 + mr]);
                af[mt2][3] = pack_bf16x2(As[rb + mr + 8], As[rb + 132 + mr + 8]);
            }
#pragma unroll
            for (int ct = 0; ct < 8; ++ct) {
                int cr = c_off + ct * 8 + lr;
                uint32_t b0 = Bs[(qb + lc) * 136 + cr];
                uint32_t b1 = Bs[(qb + 4 + lc) * 136 + cr];
                mma_bf16(d[0][ct], af[0], b0, b1);
                mma_bf16(d[1][ct], af[1], b0, b1);
            }
        }
        __syncthreads();
    }

    // ---- epilogue ----
    float* Sr = (float*)(smem + SM_R);
    Sr[tid] = massA;
    __syncthreads();
    if (tid < 128) atomicAdd(&gMass[m0 + tid], massA + Sr[tid + 128]);
    __syncthreads();
    Sr[tid] = wyA;
    __syncthreads();
    if (tid < 128) atomicAdd(&gWy[m0 + tid], wyA + Sr[tid + 128]);

#pragma unroll
    for (int mt2 = 0; mt2 < 2; ++mt2) {
#pragma unroll
        for (int ct = 0; ct < 8; ++ct) {
#pragma unroll
            for (int i = 0; i < 4; ++i) {
                int row = m0 + m_off + mt2 * 16 + lr + ((i >> 1) * 8);
                int col = c_off + ct * 8 + lc * 2 + (i & 1);
                atomicAdd(&gS[row * C_DIM + col], d[mt2][ct][i]);
            }
        }
    }
}

// ---------------- Kernel 2: per-feature finalize + fused writeout ----------------
__global__ void k2_finalize(float* out, int out_size) {
    __shared__ float cent[K_BINS][C_DIM];
    __shared__ float s_csq[K_BINS];
    __shared__ float wRep[8];
    __shared__ float wInt[8];

    int f = blockIdx.x;
    int tid = threadIdx.x;
    int w = tid >> 5, lane = tid & 31;

    for (int idx = tid; idx < K_BINS * C_DIM; idx += 256) {
        int k = idx >> 7;
        int c = idx & 127;
        float bm = gMass[f * K_BINS + k] + EPSV;
        cent[k][c] = gS[(f * K_BINS + k) * C_DIM + c] / bm;
    }
    __syncthreads();

    for (int k = w; k < K_BINS; k += 8) {
        float s = 0.0f;
#pragma unroll
        for (int j = 0; j < 4; ++j) {
            float v = cent[k][lane + 32 * j];
            s += v * v;
        }
        s = warp_sum(s);
        if (lane == 0) s_csq[k] = s;
    }
    __syncthreads();

    if (w == 0) {
        int k = lane;
        float bm = gMass[f * K_BINS + k] + EPSV;
        float wv = gWy[f * K_BINS + k] / bm - s_csq[k] * (1.0f + EPSV / bm);
        float p = bm / (float)N_SAMPLES;
        float ent = p * logf(p + EPSV);
        float dsum = warp_sum(wv);
        float esum = warp_sum(ent);
        if (lane == 0) {
            atomicAdd(&gOut[0], dsum);
            atomicAdd(&gOut[1], esum);
        }
    }

    float repP = 0.0f;
    for (int p = w; p < K_BINS - 1; p += 8) {
        float s = 0.0f;
#pragma unroll
        for (int j = 0; j < 4; ++j) {
            int c = lane + 32 * j;
            float dd = cent[p][c] - cent[p + 1][c];
            s += dd * dd;
        }
        s = warp_sum(s);
        if (lane == 0) repP += expf(-s);
    }

    float intP = 0.0f;
    for (int k = 0; k < K_BINS - 1; ++k) {
        for (int j = k + 1 + w; j < K_BINS; j += 8) {
            float s = 0.0f;
#pragma unroll
            for (int jj = 0; jj < 4; ++jj) {
                int c = lane + 32 * jj;
                float dd = cent[k][c] - cent[j][c];
                s += dd * dd;
            }
            s = warp_sum(s);
            if (lane == 0) intP += expf(-s);
        }
    }
    if (lane == 0) { wRep[w] = repP; wInt[w] = intP; }
    __syncthreads();

    if (tid == 0) {
        float rep = 0.0f, inter = 0.0f;
        for (int i = 0; i < 8; ++i) { rep += wRep[i]; inter += wInt[i]; }
        atomicAdd(&gOut[2], rep);
        atomicAdd(&gOut[3], inter);
        __threadfence();
        int done = atomicAdd(&gDone, 1);
        if (done == F_DIM - 1) {
            float disp  = atomicAdd(&gOut[0], 0.0f);
            float ent   = atomicAdd(&gOut[1], 0.0f);
            float repT  = atomicAdd(&gOut[2], 0.0f);
            float intT  = atomicAdd(&gOut[3], 0.0f) / (float)F_DIM;
            float total = disp + 0.1f * ent + 0.5f * repT + 0.3f * intT;
            float vals[5] = {total, disp, ent, repT, intT};
            for (int i = 0; i < out_size; ++i) out[i] = (i < 5) ? vals[i] : 0.0f;
        }
    }
}

extern "C" void kernel_launch(void* const* d_in, const int* in_sizes, int n_in,
                              void* d_out, int out_size) {
    const float* p0 = (const float*)d_in[0];
    const float* p1 = (const float*)d_in[1];
    const float* membership = p0;
    const float* teacher = p1;
    if (n_in >= 2 && in_sizes[0] < in_sizes[1]) {
        membership = p1;
        teacher = p0;
    }
    cudaFuncSetAttribute(k1_main, cudaFuncAttributeMaxDynamicSharedMemorySize, SM_TOTAL);
    k0_init<<<2048, 256>>>(teacher);
    k1_main<<<SPLITS * 16, 256, SM_TOTAL>>>(membership);
    k2_finalize<<<F_DIM, 256>>>((float*)d_out, out_size);
}

// round 3
// speedup vs baseline: 1.1265x; 1.0024x over previous
#include <cuda_runtime.h>
#include <cuda_bf16.h>
#include <math.h>
#include <stdint.h>

#define N_SAMPLES 16384
#define F_DIM 64
#define K_BINS 32
#define M_DIM 2048        // F*K
#define C_DIM 128
#define EPSV 1e-8f
#define SPLITS 16
#define L_CHUNK 1024      // N_SAMPLES / SPLITS
#define NIT 32            // L_CHUNK / 32

// ---- dynamic smem layout (bytes) ----
// A fp32 double buffer: 2 x [32][132] floats = 33792
// B bf16x2 double buffer: 2 x [16][136] u32  = 17408
// ysq double buffer: 2 x [32] floats         = 256
// reduction buffer: [256] floats             = 1024
#define SM_A     0
#define SM_B     33792
#define SM_Y     51200
#define SM_R     51456
#define SM_TOTAL 52480
#define A_BUF_F  4224      // floats per A buffer (32*132)
#define B_BUF_W  2176      // u32 per B buffer (16*136)

// -------- device scratch --------
__device__ float    gS[M_DIM * C_DIM];
__device__ float    gMass[M_DIM];
__device__ float    gWy[M_DIM];
__device__ float    gYsq[N_SAMPLES];
__device__ uint32_t gTpack[(N_SAMPLES / 2) * C_DIM];  // teacher bf16, n-pairs packed
__device__ float    gOut[4];
__device__ int      gDone;

__device__ __forceinline__ float warp_sum(float v) {
    v += __shfl_xor_sync(0xffffffffu, v, 16);
    v += __shfl_xor_sync(0xffffffffu, v, 8);
    v += __shfl_xor_sync(0xffffffffu, v, 4);
    v += __shfl_xor_sync(0xffffffffu, v, 2);
    v += __shfl_xor_sync(0xffffffffu, v, 1);
    return v;
}

__device__ __forceinline__ uint32_t pack_bf16x2(float lo, float hi) {
    __nv_bfloat162 t = __floats2bfloat162_rn(lo, hi);
    return *reinterpret_cast<uint32_t*>(&t);
}

__device__ __forceinline__ void mma_bf16(float* d, const uint32_t* a,
                                         uint32_t b0, uint32_t b1) {
    asm volatile(
        "mma.sync.aligned.m16n8k16.row.col.f32.bf16.bf16.f32 "
        "{%0,%1,%2,%3}, {%4,%5,%6,%7}, {%8,%9}, {%0,%1,%2,%3};\n"
        : "+f"(d[0]), "+f"(d[1]), "+f"(d[2]), "+f"(d[3])
        : "r"(a[0]), "r"(a[1]), "r"(a[2]), "r"(a[3]), "r"(b0), "r"(b1));
}

__device__ __forceinline__ void cp16(uint32_t dst, const void* src) {
    asm volatile("cp.async.cg.shared.global [%0], [%1], 16;\n" :: "r"(dst), "l"(src));
}

// ---------------- Kernel 0: zero + y_sq + prepack teacher ----------------
__global__ void k0_init(const float* __restrict__ teacher) {
    int tid = threadIdx.x;
    int idx = blockIdx.x * 256 + tid;            // 0 .. 524287
    if (idx < M_DIM * C_DIM) gS[idx] = 0.0f;
    if (idx < M_DIM) { gMass[idx] = 0.0f; gWy[idx] = 0.0f; }
    if (idx < 4) gOut[idx] = 0.0f;
    if (idx == 4) gDone = 0;

    // y_sq: one warp per sample row
    int n = idx >> 5;
    int lane = tid & 31;
    if (n < N_SAMPLES) {
        float4 v = reinterpret_cast<const float4*>(teacher)[n * 32 + lane];
        float s = v.x * v.x + v.y * v.y + v.z * v.z + v.w * v.w;
        s = warp_sum(s);
        if (lane == 0) gYsq[n] = s;
    }

    // prepack teacher: 1,048,576 words, 2 per thread
#pragma unroll
    for (int j = 0; j < 2; ++j) {
        int w = idx + j * 524288;
        int np = w >> 7;
        int c = w & 127;
        gTpack[w] = pack_bf16x2(teacher[(2 * np) * C_DIM + c],
                                teacher[(2 * np + 1) * C_DIM + c]);
    }
}

// ---------------- Kernel 1: pipelined bf16-MMA GEMM + mass/wy ----------------
__global__ void __launch_bounds__(256, 2)
k1_main(const float* __restrict__ membership) {
    extern __shared__ char smem[];
    uint32_t sb = (uint32_t)__cvta_generic_to_shared(smem);

    int tid = threadIdx.x;
    int mt = blockIdx.x & 15;
    int sp = blockIdx.x >> 4;
    int m0 = mt * 128;
    int nbeg = sp * L_CHUNK;

    int w = tid >> 5, lane = tid & 31;
    int m_off = (w & 3) * 32;
    int c_off = (w >> 2) * 64;
    int lr = lane >> 2, lc = lane & 3;

    int mmy = tid & 127;
    int h = tid >> 7;

    float d[2][8][4];
#pragma unroll
    for (int i = 0; i < 2; ++i)
#pragma unroll
        for (int j = 0; j < 8; ++j)
#pragma unroll
            for (int t = 0; t < 4; ++t) d[i][j][t] = 0.0f;
    float massA = 0.0f, wyA = 0.0f;

    // staging indices
    int sr = tid >> 3;   // 0..31  (A row)
    int scg = tid & 7;   // 0..7   (A 16B chunk group)

    auto stage = [&](int it, int buf) {
        int n0 = nbeg + it * 32;
        // A: 32 rows x 128 floats (fp32), 4 chunks/thread, octet-conflict-free
        const float* srcA = membership + (size_t)(n0 + sr) * M_DIM + m0 + scg * 4;
        uint32_t dA = sb + SM_A + buf * (A_BUF_F * 4) + sr * 528 + scg * 16;
        cp16(dA, srcA);
        cp16(dA + 128, srcA + 32);
        cp16(dA + 256, srcA + 64);
        cp16(dA + 384, srcA + 96);
        // B: 16 qpair rows x 128 u32 from gTpack, 2 chunks/thread
        int np0 = n0 >> 1;
        {
            int row = tid >> 5, cc = tid & 31;
            cp16(sb + SM_B + buf * (B_BUF_W * 4) + row * 544 + cc * 16,
                 gTpack + (np0 + row) * C_DIM + cc * 4);
            int cid = tid + 256;
            row = cid >> 5; cc = cid & 31;
            cp16(sb + SM_B + buf * (B_BUF_W * 4) + row * 544 + cc * 16,
                 gTpack + (np0 + row) * C_DIM + cc * 4);
        }
        // ysq: 32 floats
        if (tid < 8)
            cp16(sb + SM_Y + buf * 128 + tid * 16, gYsq + n0 + tid * 4);
    };

    stage(0, 0);
    asm volatile("cp.async.commit_group;\n");

    for (int it = 0; it < NIT; ++it) {
        int cur = it & 1;
        if (it + 1 < NIT) {
            stage(it + 1, cur ^ 1);
            asm volatile("cp.async.commit_group;\n");
            asm volatile("cp.async.wait_group 1;\n");
        } else {
            asm volatile("cp.async.wait_group 0;\n");
        }
        __syncthreads();

        const float* As = (const float*)(smem) + cur * A_BUF_F;
        const uint32_t* Bs = (const uint32_t*)(smem + SM_B) + cur * B_BUF_W;
        const float* Ys = (const float*)(smem + SM_Y) + cur * 32;

        // ---- fp32 mass / wy ----
#pragma unroll
        for (int qq = 0; qq < 8; ++qq) {
            int qi = h * 8 + qq;
            float ae = As[(2 * qi) * 132 + mmy];
            float ao = As[(2 * qi + 1) * 132 + mmy];
            massA += ae + ao;
            wyA += ae * Ys[2 * qi] + ao * Ys[2 * qi + 1];
        }

        // ---- MMA: 2 k-sub-steps x 16 mmas ----
#pragma unroll
        for (int ks = 0; ks < 2; ++ks) {
            int qb = ks * 8;
            uint32_t af[2][4];
#pragma unroll
            for (int mt2 = 0; mt2 < 2; ++mt2) {
                int mr = m_off + mt2 * 16 + lr;
                int ra = 2 * (qb + lc) * 132;
                int rb = 2 * (qb + 4 + lc) * 132;
                af[mt2][0] = pack_bf16x2(As[ra + mr], As[ra + 132 + mr]);
                af[mt2][1] = pack_bf16x2(As[ra + mr + 8], As[ra + 132 + mr + 8]);
                af[mt2][2] = pack_bf16x2(As[rb + mr], As[rb + 132 + mr]);
                af[mt2][3] = pack_bf16x2(As[rb + mr + 8], As[rb + 132 + mr + 8]);
            }
#pragma unroll
            for (int ct = 0; ct < 8; ++ct) {
                int cr = c_off + ct * 8 + lr;
                uint32_t b0 = Bs[(qb + lc) * 136 + cr];
                uint32_t b1 = Bs[(qb + 4 + lc) * 136 + cr];
                mma_bf16(d[0][ct], af[0], b0, b1);
                mma_bf16(d[1][ct], af[1], b0, b1);
            }
        }
        __syncthreads();
    }

    // ---- epilogue ----
    float* Sr = (float*)(smem + SM_R);
    Sr[tid] = massA;
    __syncthreads();
    if (tid < 128) atomicAdd(&gMass[m0 + tid], massA + Sr[tid + 128]);
    __syncthreads();
    Sr[tid] = wyA;
    __syncthreads();
    if (tid < 128) atomicAdd(&gWy[m0 + tid], wyA + Sr[tid + 128]);

#pragma unroll
    for (int mt2 = 0; mt2 < 2; ++mt2) {
#pragma unroll
        for (int ct = 0; ct < 8; ++ct) {
#pragma unroll
            for (int i = 0; i < 4; ++i) {
                int row = m0 + m_off + mt2 * 16 + lr + ((i >> 1) * 8);
                int col = c_off + ct * 8 + lc * 2 + (i & 1);
                atomicAdd(&gS[row * C_DIM + col], d[mt2][ct][i]);
            }
        }
    }
}

// ---------------- Kernel 2: per-feature finalize + fused writeout ----------------
__global__ void k2_finalize(float* out, int out_size) {
    __shared__ float cent[K_BINS][C_DIM];
    __shared__ float s_csq[K_BINS];
    __shared__ float wRep[8];
    __shared__ float wInt[8];

    int f = blockIdx.x;
    int tid = threadIdx.x;
    int w = tid >> 5, lane = tid & 31;

    for (int idx = tid; idx < K_BINS * C_DIM; idx += 256) {
        int k = idx >> 7;
        int c = idx & 127;
        float bm = gMass[f * K_BINS + k] + EPSV;
        cent[k][c] = gS[(f * K_BINS + k) * C_DIM + c] / bm;
    }
    __syncthreads();

    for (int k = w; k < K_BINS; k += 8) {
        float s = 0.0f;
#pragma unroll
        for (int j = 0; j < 4; ++j) {
            float v = cent[k][lane + 32 * j];
            s += v * v;
        }
        s = warp_sum(s);
        if (lane == 0) s_csq[k] = s;
    }
    __syncthreads();

    if (w == 0) {
        int k = lane;
        float bm = gMass[f * K_BINS + k] + EPSV;
        float wv = gWy[f * K_BINS + k] / bm - s_csq[k] * (1.0f + EPSV / bm);
        float p = bm / (float)N_SAMPLES;
        float ent = p * logf(p + EPSV);
        float dsum = warp_sum(wv);
        float esum = warp_sum(ent);
        if (lane == 0) {
            atomicAdd(&gOut[0], dsum);
            atomicAdd(&gOut[1], esum);
        }
    }

    float repP = 0.0f;
    for (int p = w; p < K_BINS - 1; p += 8) {
        float s = 0.0f;
#pragma unroll
        for (int j = 0; j < 4; ++j) {
            int c = lane + 32 * j;
            float dd = cent[p][c] - cent[p + 1][c];
            s += dd * dd;
        }
        s = warp_sum(s);
        if (lane == 0) repP += expf(-s);
    }

    float intP = 0.0f;
    for (int k = 0; k < K_BINS - 1; ++k) {
        for (int j = k + 1 + w; j < K_BINS; j += 8) {
            float s = 0.0f;
#pragma unroll
            for (int jj = 0; jj < 4; ++jj) {
                int c = lane + 32 * jj;
                float dd = cent[k][c] - cent[j][c];
                s += dd * dd;
            }
            s = warp_sum(s);
            if (lane == 0) intP += expf(-s);
        }
    }
    if (lane == 0) { wRep[w] = repP; wInt[w] = intP; }
    __syncthreads();

    if (tid == 0) {
        float rep = 0.0f, inter = 0.0f;
        for (int i = 0; i < 8; ++i) { rep += wRep[i]; inter += wInt[i]; }
        atomicAdd(&gOut[2], rep);
        atomicAdd(&gOut[3], inter);
        __threadfence();
        int done = atomicAdd(&gDone, 1);
        if (done == F_DIM - 1) {
            float disp  = atomicAdd(&gOut[0], 0.0f);
            float ent   = atomicAdd(&gOut[1], 0.0f);
            float repT  = atomicAdd(&gOut[2], 0.0f);
            float intT  = atomicAdd(&gOut[3], 0.0f) / (float)F_DIM;
            float total = disp + 0.1f * ent + 0.5f * repT + 0.3f * intT;
            float vals[5] = {total, disp, ent, repT, intT};
            for (int i = 0; i < out_size; ++i) out[i] = (i < 5) ? vals[i] : 0.0f;
        }
    }
}

extern "C" void kernel_launch(void* const* d_in, const int* in_sizes, int n_in,
                              void* d_out, int out_size) {
    const float* p0 = (const float*)d_in[0];
    const float* p1 = (const float*)d_in[1];
    const float* membership = p0;
    const float* teacher = p1;
    if (n_in >= 2 && in_sizes[0] < in_sizes[1]) {
        membership = p1;
        teacher = p0;
    }
    cudaFuncSetAttribute(k1_main, cudaFuncAttributeMaxDynamicSharedMemorySize, SM_TOTAL);
    k0_init<<<2048, 256>>>(teacher);
    k1_main<<<SPLITS * 16, 256, SM_TOTAL>>>(membership);
    k2_finalize<<<F_DIM, 256>>>((float*)d_out, out_size);
}